// round 15
// baseline (speedup 1.0000x reference)
#include <cuda_runtime.h>
#include <cuda_fp16.h>
#include <cstdint>
#include <math.h>

#define B_ 512
#define T_ 96
#define F_ 128
#define H_ 512
#define TB_ (T_*B_)        // 49152
#define BTF_ (B_*T_*F_)    // 6291456
#define KG_ 768            // gates GEMM K = 2F + H
#define NG_ 2048           // 4H
#define NCTA 128

typedef unsigned int u32;

// ---------------- scratch (device globals: no allocation allowed) ----------------
__device__ __align__(16) __half g_d16[TB_*F_];
__device__ float g_gammah[TB_*H_];
__device__ __align__(16) __half g_A216[TB_*2*F_];
__device__ float g_alpha[TB_*F_];
__device__ __align__(16) __half g_A16[B_*KG_];     // [c_c | m | h*gamma]
__device__ float g_c[B_*H_];
__device__ float g_h[B_*H_];
__device__ float g_Gh[B_*NG_];                     // partial gates from h-slice
__device__ __align__(16) __half g_Wg16[NG_*KG_];   // gate-interleaved
__device__ float g_bgR[NG_];
__device__ __align__(16) __half g_Wdh16[H_*F_];
__device__ __align__(16) __half g_WdhR[H_*F_];
__device__ __align__(16) __half g_Wc16[F_*2*F_];
__device__ __align__(16) __half g_WcR[F_*2*F_];
__device__ __align__(16) __half2 g_Wh2[256*128];   // Wh packed [k2][n]
__device__ __align__(16) __half2 g_Wf2[64*128];    // Wf packed [k2][n]
__device__ float g_wfdiag[128];
__device__ unsigned g_barcnt;
__device__ volatile unsigned g_bargen;

__device__ __forceinline__ float sigmoidf_(float v){ return 1.f/(1.f+expf(-v)); }

__device__ __forceinline__ u32 sptr(const void* p){
    return (u32)__cvta_generic_to_shared(p);
}

__device__ __forceinline__ void ldsm4(u32* r, u32 addr){
    asm volatile("ldmatrix.sync.aligned.m8n8.x4.shared.b16 {%0,%1,%2,%3}, [%4];"
        : "=r"(r[0]),"=r"(r[1]),"=r"(r[2]),"=r"(r[3]) : "r"(addr));
}

__device__ __forceinline__ void mma16816h(float* c, const u32* a, u32 b0, u32 b1){
    asm volatile("mma.sync.aligned.m16n8k16.row.col.f32.f16.f16.f32 "
        "{%0,%1,%2,%3},{%4,%5,%6,%7},{%8,%9},{%0,%1,%2,%3};"
        : "+f"(c[0]),"+f"(c[1]),"+f"(c[2]),"+f"(c[3])
        : "r"(a[0]),"r"(a[1]),"r"(a[2]),"r"(a[3]), "r"(b0),"r"(b1));
}

__device__ __forceinline__ void cpasync16(u32 dst, const void* src){
    asm volatile("cp.async.cg.shared.global [%0], [%1], 16;" :: "r"(dst), "l"(src));
}

__device__ __forceinline__ void gridsync(){
    __syncthreads();
    __threadfence();
    if (threadIdx.x == 0){
        unsigned gen = g_bargen;
        if (atomicAdd(&g_barcnt, 1u) == NCTA-1u){
            g_barcnt = 0;
            __threadfence();
            g_bargen = gen + 1u;
        } else {
            while (g_bargen == gen) { }
        }
    }
    __syncthreads();
    __threadfence();
}

// ---------------- setup ----------------
__global__ void k_setup(const float* __restrict__ Wih, const float* __restrict__ Whh,
                        const float* __restrict__ bih, const float* __restrict__ bhh,
                        const float* __restrict__ Wdh, const float* __restrict__ Wc,
                        const float* __restrict__ Wh, const float* __restrict__ Wf){
    int tid0 = blockIdx.x*blockDim.x + threadIdx.x;
    int stride = gridDim.x*blockDim.x;
    for (int idx = tid0; idx < NG_*KG_; idx += stride){
        int n = idx / KG_;
        int k = idx - n*KG_;
        int j = n >> 2, g = n & 3;
        int no = g*512 + j;
        float v = (k < 256) ? Wih[no*256 + k] : Whh[no*H_ + (k-256)];
        g_Wg16[idx] = __float2half(v);
    }
    for (int idx = tid0; idx < H_*F_; idx += stride){
        float v = Wdh[idx];
        __half h = __float2half(v);
        g_Wdh16[idx] = h;
        g_WdhR[idx]  = __float2half((v - __half2float(h))*1024.f);
    }
    for (int idx = tid0; idx < F_*2*F_; idx += stride){
        float v = Wc[idx];
        __half h = __float2half(v);
        g_Wc16[idx] = h;
        g_WcR[idx]  = __float2half((v - __half2float(h))*1024.f);
    }
    for (int idx = tid0; idx < 256*128; idx += stride){
        int k2 = idx >> 7, n = idx & 127;
        g_Wh2[idx] = __floats2half2_rn(Wh[n*H_ + 2*k2], Wh[n*H_ + 2*k2 + 1]);
    }
    for (int idx = tid0; idx < 64*128; idx += stride){
        int k2 = idx >> 7, n = idx & 127;
        g_Wf2[idx] = __floats2half2_rn(Wf[n*F_ + 2*k2], Wf[n*F_ + 2*k2 + 1]);
    }
    for (int idx = tid0; idx < B_*H_; idx += stride){
        g_c[idx] = 0.f;
        g_h[idx] = 0.f;
        g_A16[(idx >> 9)*KG_ + 256 + (idx & 511)] = __float2half(0.f);
    }
    if (tid0 < NG_){
        int j = tid0 >> 2, g = tid0 & 3;
        int no = g*512 + j;
        g_bgR[tid0] = bih[no] + bhh[no];
    }
    if (tid0 < 128)
        g_wfdiag[tid0] = __half2float(__float2half(Wf[tid0*F_ + tid0]));
}

// ---------------- delta scan + gamma_x + alpha-input (fused) ----------------
__global__ void k_delta2(const int* __restrict__ mask, const float* __restrict__ Wdx,
                         const float* __restrict__ bdx){
    int idx = blockIdx.x*blockDim.x + threadIdx.x;
    int b = idx >> 7, f = idx & 127;
    const float wdx = Wdx[f*F_ + f];
    const float bx  = bdx[f];
    const int base = b*T_*F_ + f;
    float d = 0.f;
    for (int t = 0; t < T_; t++){
        int o = t*B_ + b;
        g_d16[o*F_ + f] = __float2half(d);
        float gx = expf(-fmaxf(d*wdx + bx, 0.f));
        float mp = (float)mask[base + t*F_];
        g_A216[o*256 + f]       = __float2half(gx);
        g_A216[o*256 + 128 + f] = __float2half(mp);
        d = mp + (1.f - mp)*(d + 1.f);
    }
}

// ---------------- 2-pass fp16 GEMM (precompute) ----------------
#define SSTR 72
#define R2P 320
#define B2P (R2P*SSTR)
#define SM2P (2*B2P*2)

template<int EPI>
__global__ void __launch_bounds__(256, 1)
gemm_2p(const __half* __restrict__ A, const __half* __restrict__ W,
        const __half* __restrict__ Wr, const float* __restrict__ bias,
        float* __restrict__ C, int N, int K)
{
    extern __shared__ __align__(16) __half smh[];
    const int tid = threadIdx.x, lane = tid & 31, wid = tid >> 5;
    const int m0 = blockIdx.y*64, n0 = blockIdx.x*128;
    const int wm = (wid & 1)*32, wn = (wid >> 1)*32;
    const int NC = K >> 6;

    float acc1[2][4][4], acc2[2][4][4];
    #pragma unroll
    for (int i=0;i<2;i++)
        #pragma unroll
        for (int j=0;j<4;j++)
            #pragma unroll
            for (int q=0;q<4;q++){ acc1[i][j][q]=0.f; acc2[i][j][q]=0.f; }

    const int aRow = lane & 15;
    const int aCol = ((lane >> 4) & 1) * 8;
    const int bRow = (lane & 7) + ((lane >> 4) & 1) * 8;
    const int bCol = ((lane >> 3) & 1) * 8;

    const __half* s_src[10]; int s_row[10];
    #pragma unroll
    for (int j = 0; j < 10; j++){
        int u = tid + j*256; int r = u >> 3;
        if (r < 64)      { s_src[j] = A;  s_row[j] = m0 + r; }
        else if (r < 192){ s_src[j] = W;  s_row[j] = n0 + r - 64; }
        else             { s_src[j] = Wr; s_row[j] = n0 + r - 192; }
    }

    {
        #pragma unroll
        for (int j = 0; j < 10; j++){
            int u = tid + j*256; int r = u >> 3, c = (u & 7)*8;
            cpasync16(sptr(&smh[r*SSTR + c]), &s_src[j][(size_t)s_row[j]*K + c]);
        }
        asm volatile("cp.async.commit_group;" ::: "memory");
    }

    for (int ch = 0; ch < NC; ch++){
        if (ch + 1 < NC){
            __half* tb = smh + ((ch+1)&1)*B2P;
            const int k1 = (ch+1)*64;
            #pragma unroll
            for (int j = 0; j < 10; j++){
                int u = tid + j*256; int r = u >> 3, c = (u & 7)*8;
                cpasync16(sptr(&tb[r*SSTR + c]), &s_src[j][(size_t)s_row[j]*K + k1 + c]);
            }
            asm volatile("cp.async.commit_group;" ::: "memory");
            asm volatile("cp.async.wait_group 1;" ::: "memory");
        } else {
            asm volatile("cp.async.wait_group 0;" ::: "memory");
        }
        __syncthreads();

        const __half* bb = smh + (ch&1)*B2P;
        const __half* As = bb;
        const __half* Ws = bb + 64*SSTR;
        const __half* Rs = bb + 192*SSTR;

        #pragma unroll
        for (int kk = 0; kk < 64; kk += 16){
            u32 a[2][4], bw[2][4], br[2][4];
            #pragma unroll
            for (int mt = 0; mt < 2; mt++)
                ldsm4(a[mt], sptr(&As[(wm + mt*16 + aRow)*SSTR + kk + aCol]));
            #pragma unroll
            for (int nt = 0; nt < 2; nt++){
                ldsm4(bw[nt], sptr(&Ws[(wn + nt*16 + bRow)*SSTR + kk + bCol]));
                ldsm4(br[nt], sptr(&Rs[(wn + nt*16 + bRow)*SSTR + kk + bCol]));
            }
            #pragma unroll
            for (int mt = 0; mt < 2; mt++)
                #pragma unroll
                for (int nj = 0; nj < 4; nj++){
                    const u32* pw = &bw[nj >> 1][(nj & 1) * 2];
                    const u32* pr = &br[nj >> 1][(nj & 1) * 2];
                    mma16816h(acc1[mt][nj], a[mt], pw[0], pw[1]);
                    mma16816h(acc2[mt][nj], a[mt], pr[0], pr[1]);
                }
        }
        __syncthreads();
    }

    const float rs = 1.f/1024.f;
    #pragma unroll
    for (int mt = 0; mt < 2; mt++){
        int row = m0 + wm + mt*16 + (lane >> 2);
        #pragma unroll
        for (int nj = 0; nj < 4; nj++){
            int col = n0 + wn + nj*8 + (lane & 3)*2;
            float b0v = bias[col], b1v = bias[col+1];
            float v[4] = { acc1[mt][nj][0] + acc2[mt][nj][0]*rs + b0v,
                           acc1[mt][nj][1] + acc2[mt][nj][1]*rs + b1v,
                           acc1[mt][nj][2] + acc2[mt][nj][2]*rs + b0v,
                           acc1[mt][nj][3] + acc2[mt][nj][3]*rs + b1v };
            #pragma unroll
            for (int q = 0; q < 4; q++){
                if (EPI == 1)      v[q] = expf(-fmaxf(v[q], 0.f));
                else if (EPI == 2) v[q] = 1.f/(1.f+expf(-v[q]));
            }
            C[(size_t)row*N + col]         = v[0];
            C[(size_t)row*N + col + 1]     = v[1];
            C[(size_t)(row+8)*N + col]     = v[2];
            C[(size_t)(row+8)*N + col + 1] = v[3];
        }
    }
}

// ---------------- persistent recurrence kernel (warp-specialized) ----------------
// smem: [wh2 131072][wf2 32768][wfd 512][phaseA 12288][staging 55296] = 231936 B
#define WH_OFF  0
#define WF_OFF  131072
#define WFD_OFF 163840
#define SCR_A   164352
#define SCR_G   (SCR_A + 12288)
#define BGH     (192*SSTR)           // halfs per staging buffer (13824)
#define SMR     (SCR_G + 2*BGH*2)    // 231936 bytes

__global__ void __launch_bounds__(256, 1)
k_recur(const float* __restrict__ x, const int* __restrict__ mask,
        const float* __restrict__ bh, const float* __restrict__ bf,
        float* __restrict__ out)
{
    extern __shared__ __align__(16) char sm[];
    const int tid = threadIdx.x, lane = tid & 31, wid = tid >> 5;
    const int bid = blockIdx.x;

    __half2* wh2 = (__half2*)(sm + WH_OFF);
    __half2* wf2 = (__half2*)(sm + WF_OFF);
    float*   wfd = (float*)(sm + WFD_OFF);
    float* hs   = (float*)(sm + SCR_A);      // [4][512]
    float* xh_s = hs + 4*512;                // [4][128]
    float* xc_s = xh_s + 4*128;              // [4][128]
    __half* smG = (__half*)(sm + SCR_G);     // staging (Gh / Gc) + Cs overlay

    for (int idx = tid; idx < 256*128; idx += 256) wh2[idx] = g_Wh2[idx];
    for (int idx = tid; idx < 64*128;  idx += 256) wf2[idx] = g_Wf2[idx];
    if (tid < 128) wfd[tid] = g_wfdiag[tid];
    __syncthreads();

    const int b0 = bid << 2;                 // phase A: 4 batches/CTA
    const int m0 = (bid >> 4)*64;            // GEMM tile
    const int n0 = (bid & 15)*128;
    const int aRow = lane & 15;
    const int aCol = ((lane >> 4) & 1) * 8;
    const int bRow = (lane & 7) + ((lane >> 4) & 1) * 8;
    const int bCol = ((lane >> 3) & 1) * 8;

    for (int t = 0; t < T_; t++){
        if (wid < 4){
            // ===== phase A: step work (128 threads, FMA/LDS pipes) =====
            const int n = tid;               // 0..127
            for (int idx = tid; idx < 2048; idx += 128)
                hs[idx] = g_h[b0*H_ + idx];
            asm volatile("bar.sync 1, 128;" ::: "memory");

            float acc[4] = {0.f,0.f,0.f,0.f};
            #pragma unroll 4
            for (int k2 = 0; k2 < 256; k2++){
                float2 w = __half22float2(wh2[k2*128 + n]);
                #pragma unroll
                for (int b = 0; b < 4; b++){
                    float2 hv = *(const float2*)&hs[b*512 + 2*k2];
                    acc[b] += w.x*hv.x + w.y*hv.y;
                }
            }

            float m_r[4], x_r[4];
            {
                float bhv = bh[n];
                #pragma unroll
                for (int b = 0; b < 4; b++){
                    int gb = b0 + b;
                    float xh = acc[b] + bhv;
                    xh_s[b*128 + n] = xh;
                    int gi = gb*T_*F_ + t*F_ + n;
                    float mv = (float)mask[gi];
                    float xv = x[gi];
                    m_r[b] = mv; x_r[b] = xv;
                    xc_s[b*128 + n] = mv*xv + (1.f - mv)*xh;
                    out[3*BTF_ + gi] = xh;
                }
            }
            asm volatile("bar.sync 1, 128;" ::: "memory");

            float acc2[4] = {0.f,0.f,0.f,0.f};
            #pragma unroll 4
            for (int k2 = 0; k2 < 64; k2++){
                float2 w = __half22float2(wf2[k2*128 + n]);
                #pragma unroll
                for (int b = 0; b < 4; b++){
                    float2 cv = *(const float2*)&xc_s[b*128 + 2*k2];
                    acc2[b] += w.x*cv.x + w.y*cv.y;
                }
            }

            {
                float bfv = bf[n];
                float wfdv = wfd[n];
                #pragma unroll
                for (int b = 0; b < 4; b++){
                    int gb = b0 + b;
                    float xc = xc_s[b*128 + n];
                    float z  = acc2[b] + bfv - xc*wfdv;
                    float al = g_alpha[(size_t)(t*B_ + gb)*F_ + n];
                    float xh = xh_s[b*128 + n];
                    float ch = al*z + (1.f - al)*xh;
                    float cc = m_r[b]*x_r[b] + (1.f - m_r[b])*ch;
                    int gi = gb*T_*F_ + t*F_ + n;
                    out[gi]          = cc;
                    out[BTF_  + gi]  = ch;
                    out[2*BTF_+ gi]  = z;
                    g_A16[gb*KG_ + n]       = __float2half(cc);
                    g_A16[gb*KG_ + 128 + n] = __float2half(m_r[b]);
                }
            }
        } else if (t < T_ - 1){
            // ===== Gh GEMM: hγ @ Wg[:,256:]^T (K=512), 4 warps, tensor pipe =====
            const int gtid = tid - 128;      // 0..127
            const int gwid = wid - 4;        // 0..3
            const int wm = (gwid & 1)*32, wn = (gwid >> 1)*64;
            const __half* Asrc = g_A16 + 256;
            const __half* Wsrc = g_Wg16 + 256;

            float gacc[2][8][4];
            #pragma unroll
            for (int i=0;i<2;i++)
                #pragma unroll
                for (int j=0;j<8;j++)
                    #pragma unroll
                    for (int q=0;q<4;q++) gacc[i][j][q] = 0.f;

            {
                #pragma unroll
                for (int j = 0; j < 12; j++){
                    int u = gtid + j*128; int r = u >> 3, c = (u & 7)*8;
                    const __half* src = (r < 64) ? Asrc : Wsrc;
                    int row = (r < 64) ? (m0 + r) : (n0 + r - 64);
                    cpasync16(sptr(&smG[r*SSTR + c]), &src[(size_t)row*KG_ + c]);
                }
                asm volatile("cp.async.commit_group;" ::: "memory");
            }

            for (int ch = 0; ch < 8; ch++){
                if (ch + 1 < 8){
                    __half* tb = smG + ((ch+1)&1)*BGH;
                    const int k1 = (ch+1)*64;
                    #pragma unroll
                    for (int j = 0; j < 12; j++){
                        int u = gtid + j*128; int r = u >> 3, c = (u & 7)*8;
                        const __half* src = (r < 64) ? Asrc : Wsrc;
                        int row = (r < 64) ? (m0 + r) : (n0 + r - 64);
                        cpasync16(sptr(&tb[r*SSTR + c]), &src[(size_t)row*KG_ + k1 + c]);
                    }
                    asm volatile("cp.async.commit_group;" ::: "memory");
                    asm volatile("cp.async.wait_group 1;" ::: "memory");
                } else {
                    asm volatile("cp.async.wait_group 0;" ::: "memory");
                }
                asm volatile("bar.sync 2, 128;" ::: "memory");

                const __half* bb = smG + (ch&1)*BGH;
                const __half* As = bb;
                const __half* Ws = bb + 64*SSTR;

                #pragma unroll
                for (int kk = 0; kk < 64; kk += 16){
                    u32 a[2][4], b[4][4];
                    #pragma unroll
                    for (int mt = 0; mt < 2; mt++)
                        ldsm4(a[mt], sptr(&As[(wm + mt*16 + aRow)*SSTR + kk + aCol]));
                    #pragma unroll
                    for (int nt = 0; nt < 4; nt++)
                        ldsm4(b[nt], sptr(&Ws[(wn + nt*16 + bRow)*SSTR + kk + bCol]));
                    #pragma unroll
                    for (int mt = 0; mt < 2; mt++)
                        #pragma unroll
                        for (int nj = 0; nj < 8; nj++){
                            const u32* pb = &b[nj >> 1][(nj & 1) * 2];
                            mma16816h(gacc[mt][nj], a[mt], pb[0], pb[1]);
                        }
                }
                asm volatile("bar.sync 2, 128;" ::: "memory");
            }

            #pragma unroll
            for (int mt = 0; mt < 2; mt++){
                int row = m0 + wm + mt*16 + (lane >> 2);
                #pragma unroll
                for (int nj = 0; nj < 8; nj++){
                    int col = n0 + wn + nj*8 + (lane & 3)*2;
                    g_Gh[(size_t)row*NG_ + col]         = gacc[mt][nj][0];
                    g_Gh[(size_t)row*NG_ + col + 1]     = gacc[mt][nj][1];
                    g_Gh[(size_t)(row+8)*NG_ + col]     = gacc[mt][nj][2];
                    g_Gh[(size_t)(row+8)*NG_ + col + 1] = gacc[mt][nj][3];
                }
            }
        }

        if (t == T_ - 1) break;
        gridsync();

        // ===== phase B: Gc = [c_c|m] @ Wg[:,0:256]^T (K=256) + Gh + LSTM =====
        {
            const int wm = (wid & 1)*32, wn = (wid >> 1)*32;
            float acc[2][4][4];
            #pragma unroll
            for (int i=0;i<2;i++)
                #pragma unroll
                for (int j=0;j<4;j++)
                    #pragma unroll
                    for (int q=0;q<4;q++) acc[i][j][q] = 0.f;

            {
                #pragma unroll
                for (int j = 0; j < 6; j++){
                    int u = tid + j*256; int r = u >> 3, c = (u & 7)*8;
                    const __half* src = (r < 64) ? g_A16 : g_Wg16;
                    int row = (r < 64) ? (m0 + r) : (n0 + r - 64);
                    cpasync16(sptr(&smG[r*SSTR + c]), &src[(size_t)row*KG_ + c]);
                }
                asm volatile("cp.async.commit_group;" ::: "memory");
            }

            for (int ch = 0; ch < 4; ch++){
                if (ch + 1 < 4){
                    __half* tb = smG + ((ch+1)&1)*BGH;
                    const int k1 = (ch+1)*64;
                    #pragma unroll
                    for (int j = 0; j < 6; j++){
                        int u = tid + j*256; int r = u >> 3, c = (u & 7)*8;
                        const __half* src = (r < 64) ? g_A16 : g_Wg16;
                        int row = (r < 64) ? (m0 + r) : (n0 + r - 64);
                        cpasync16(sptr(&tb[r*SSTR + c]), &src[(size_t)row*KG_ + k1 + c]);
                    }
                    asm volatile("cp.async.commit_group;" ::: "memory");
                    asm volatile("cp.async.wait_group 1;" ::: "memory");
                } else {
                    asm volatile("cp.async.wait_group 0;" ::: "memory");
                }
                __syncthreads();

                const __half* bb = smG + (ch&1)*BGH;
                const __half* As = bb;
                const __half* Ws = bb + 64*SSTR;

                #pragma unroll
                for (int kk = 0; kk < 64; kk += 16){
                    u32 a[2][4], b[2][4];
                    #pragma unroll
                    for (int mt = 0; mt < 2; mt++)
                        ldsm4(a[mt], sptr(&As[(wm + mt*16 + aRow)*SSTR + kk + aCol]));
                    #pragma unroll
                    for (int nt = 0; nt < 2; nt++)
                        ldsm4(b[nt], sptr(&Ws[(wn + nt*16 + bRow)*SSTR + kk + bCol]));
                    #pragma unroll
                    for (int mt = 0; mt < 2; mt++)
                        #pragma unroll
                        for (int nj = 0; nj < 4; nj++){
                            const u32* pb = &b[nj >> 1][(nj & 1) * 2];
                            mma16816h(acc[mt][nj], a[mt], pb[0], pb[1]);
                        }
                }
                __syncthreads();
            }

            // epilogue: gates = acc + bias + Gh -> LSTM update
            float* Cs = (float*)smG;   // 64x128 fp32 overlay
            #pragma unroll
            for (int mt = 0; mt < 2; mt++){
                int rl = wm + mt*16 + (lane >> 2);
                #pragma unroll
                for (int nj = 0; nj < 4; nj++){
                    int cl = wn + nj*8 + (lane & 3)*2;
                    float b0v = g_bgR[n0 + cl], b1v = g_bgR[n0 + cl + 1];
                    const float* gh0 = &g_Gh[(size_t)(m0+rl)*NG_ + n0 + cl];
                    const float* gh8 = &g_Gh[(size_t)(m0+rl+8)*NG_ + n0 + cl];
                    Cs[rl*128 + cl]         = acc[mt][nj][0] + b0v + gh0[0];
                    Cs[rl*128 + cl + 1]     = acc[mt][nj][1] + b1v + gh0[1];
                    Cs[(rl+8)*128 + cl]     = acc[mt][nj][2] + b0v + gh8[0];
                    Cs[(rl+8)*128 + cl + 1] = acc[mt][nj][3] + b1v + gh8[1];
                }
            }
            __syncthreads();

            const int u0 = n0 >> 2;
            #pragma unroll
            for (int i = 0; i < 8; i++){
                int cidx = tid + i*256;
                int bl = cidx >> 5, jl = cidx & 31;
                float4 gv = *(const float4*)&Cs[bl*128 + jl*4];   // i, f, g, o
                float ig = sigmoidf_(gv.x);
                float fg = sigmoidf_(gv.y);
                float gg = tanhf(gv.z);
                float og = sigmoidf_(gv.w);
                int gb = m0 + bl;
                int ju = u0 + jl;
                float c = fg * g_c[gb*H_ + ju] + ig*gg;
                g_c[gb*H_ + ju] = c;
                float h = og * tanhf(c);
                g_h[gb*H_ + ju] = h;
                float hd = h * g_gammah[(size_t)((t+1)*B_ + gb)*H_ + ju];
                g_A16[gb*KG_ + 256 + ju] = __float2half(hd);
            }
            __syncthreads();
        }
        gridsync();
    }
}

// ---------------- launch ----------------
extern "C" void kernel_launch(void* const* d_in, const int* in_sizes, int n_in,
                              void* d_out, int out_size)
{
    const float* x    = (const float*)d_in[0];
    const int*   mask = (const int*  )d_in[1];
    const float* Wdh  = (const float*)d_in[2];
    const float* bdh  = (const float*)d_in[3];
    const float* Wdx  = (const float*)d_in[4];
    const float* bdx  = (const float*)d_in[5];
    const float* Wh   = (const float*)d_in[6];
    const float* bh   = (const float*)d_in[7];
    const float* Wf   = (const float*)d_in[8];
    const float* bf   = (const float*)d_in[9];
    const float* Wc   = (const float*)d_in[10];
    const float* bc   = (const float*)d_in[11];
    const float* Wih  = (const float*)d_in[12];
    const float* Whh  = (const float*)d_in[13];
    const float* bih  = (const float*)d_in[14];
    const float* bhh  = (const float*)d_in[15];
    float* out = (float*)d_out;

    void *pD16, *pA216, *pWdh16, *pWdhR, *pWc16, *pWcR, *pGammah, *pAlpha;
    cudaGetSymbolAddress(&pD16,    g_d16);
    cudaGetSymbolAddress(&pA216,   g_A216);
    cudaGetSymbolAddress(&pWdh16,  g_Wdh16);
    cudaGetSymbolAddress(&pWdhR,   g_WdhR);
    cudaGetSymbolAddress(&pWc16,   g_Wc16);
    cudaGetSymbolAddress(&pWcR,    g_WcR);
    cudaGetSymbolAddress(&pGammah, g_gammah);
    cudaGetSymbolAddress(&pAlpha,  g_alpha);

    cudaFuncSetAttribute(gemm_2p<1>, cudaFuncAttributeMaxDynamicSharedMemorySize, SM2P);
    cudaFuncSetAttribute(gemm_2p<2>, cudaFuncAttributeMaxDynamicSharedMemorySize, SM2P);
    cudaFuncSetAttribute(k_recur,    cudaFuncAttributeMaxDynamicSharedMemorySize, SMR);

    // setup + time-parallel precomputes
    k_setup<<<2048, 256>>>(Wih, Whh, bih, bhh, Wdh, Wc, Wh, Wf);
    k_delta2<<<256, 256>>>(mask, Wdx, bdx);
    gemm_2p<1><<<dim3(H_/128, TB_/64), 256, SM2P>>>(
        (const __half*)pD16, (const __half*)pWdh16, (const __half*)pWdhR,
        bdh, (float*)pGammah, H_, F_);
    gemm_2p<2><<<dim3(F_/128, TB_/64), 256, SM2P>>>(
        (const __half*)pA216, (const __half*)pWc16, (const __half*)pWcR,
        bc, (float*)pAlpha, F_, 2*F_);

    // entire 96-step recurrence in ONE persistent kernel
    k_recur<<<NCTA, 256, SMR>>>(x, mask, bh, bf, out);
}

// round 16
// speedup vs baseline: 1.1116x; 1.1116x over previous
#include <cuda_runtime.h>
#include <cuda_fp16.h>
#include <cstdint>
#include <math.h>

#define B_ 512
#define T_ 96
#define F_ 128
#define H_ 512
#define TB_ (T_*B_)        // 49152
#define BTF_ (B_*T_*F_)    // 6291456
#define KG_ 768            // gates GEMM K = 2F + H
#define NG_ 2048           // 4H
#define NCTA 128

typedef unsigned int u32;

// ---------------- scratch (device globals: no allocation allowed) ----------------
__device__ __align__(16) __half g_d16[TB_*F_];
__device__ float g_gammah[TB_*H_];
__device__ __align__(16) __half g_A216[TB_*2*F_];
__device__ float g_alpha[TB_*F_];
__device__ __align__(16) __half g_A16[B_*KG_];     // [c_c | m | h*gamma]
__device__ float g_c[B_*H_];
__device__ float g_h[B_*H_];
__device__ __align__(16) __half g_Wg16[NG_*KG_];   // gate-interleaved
__device__ float g_bgR[NG_];
__device__ __align__(16) __half g_Wdh16[H_*F_];
__device__ __align__(16) __half g_WdhR[H_*F_];
__device__ __align__(16) __half g_Wc16[F_*2*F_];
__device__ __align__(16) __half g_WcR[F_*2*F_];
__device__ __align__(16) __half2 g_Wh2[256*128];   // Wh packed [k2][n]
__device__ __align__(16) __half2 g_Wf2[64*128];    // Wf packed [k2][n]
__device__ float g_wfdiag[128];
__device__ unsigned g_barcnt;
__device__ volatile unsigned g_bargen;

__device__ __forceinline__ float sigmoidf_(float v){ return 1.f/(1.f+expf(-v)); }

__device__ __forceinline__ u32 sptr(const void* p){
    return (u32)__cvta_generic_to_shared(p);
}

__device__ __forceinline__ void ldsm4(u32* r, u32 addr){
    asm volatile("ldmatrix.sync.aligned.m8n8.x4.shared.b16 {%0,%1,%2,%3}, [%4];"
        : "=r"(r[0]),"=r"(r[1]),"=r"(r[2]),"=r"(r[3]) : "r"(addr));
}

__device__ __forceinline__ void mma16816h(float* c, const u32* a, u32 b0, u32 b1){
    asm volatile("mma.sync.aligned.m16n8k16.row.col.f32.f16.f16.f32 "
        "{%0,%1,%2,%3},{%4,%5,%6,%7},{%8,%9},{%0,%1,%2,%3};"
        : "+f"(c[0]),"+f"(c[1]),"+f"(c[2]),"+f"(c[3])
        : "r"(a[0]),"r"(a[1]),"r"(a[2]),"r"(a[3]), "r"(b0),"r"(b1));
}

__device__ __forceinline__ void cpasync16(u32 dst, const void* src){
    asm volatile("cp.async.cg.shared.global [%0], [%1], 16;" :: "r"(dst), "l"(src));
}

__device__ __forceinline__ void gridsync(){
    __syncthreads();
    __threadfence();
    if (threadIdx.x == 0){
        unsigned gen = g_bargen;
        if (atomicAdd(&g_barcnt, 1u) == NCTA-1u){
            g_barcnt = 0;
            __threadfence();
            g_bargen = gen + 1u;
        } else {
            while (g_bargen == gen) { }
        }
    }
    __syncthreads();
    __threadfence();
}

// ---------------- setup ----------------
__global__ void k_setup(const float* __restrict__ Wih, const float* __restrict__ Whh,
                        const float* __restrict__ bih, const float* __restrict__ bhh,
                        const float* __restrict__ Wdh, const float* __restrict__ Wc,
                        const float* __restrict__ Wh, const float* __restrict__ Wf){
    int tid0 = blockIdx.x*blockDim.x + threadIdx.x;
    int stride = gridDim.x*blockDim.x;
    for (int idx = tid0; idx < NG_*KG_; idx += stride){
        int n = idx / KG_;
        int k = idx - n*KG_;
        int j = n >> 2, g = n & 3;
        int no = g*512 + j;
        float v = (k < 256) ? Wih[no*256 + k] : Whh[no*H_ + (k-256)];
        g_Wg16[idx] = __float2half(v);
    }
    for (int idx = tid0; idx < H_*F_; idx += stride){
        float v = Wdh[idx];
        __half h = __float2half(v);
        g_Wdh16[idx] = h;
        g_WdhR[idx]  = __float2half((v - __half2float(h))*1024.f);
    }
    for (int idx = tid0; idx < F_*2*F_; idx += stride){
        float v = Wc[idx];
        __half h = __float2half(v);
        g_Wc16[idx] = h;
        g_WcR[idx]  = __float2half((v - __half2float(h))*1024.f);
    }
    for (int idx = tid0; idx < 256*128; idx += stride){
        int k2 = idx >> 7, n = idx & 127;
        g_Wh2[idx] = __floats2half2_rn(Wh[n*H_ + 2*k2], Wh[n*H_ + 2*k2 + 1]);
    }
    for (int idx = tid0; idx < 64*128; idx += stride){
        int k2 = idx >> 7, n = idx & 127;
        g_Wf2[idx] = __floats2half2_rn(Wf[n*F_ + 2*k2], Wf[n*F_ + 2*k2 + 1]);
    }
    for (int idx = tid0; idx < B_*H_; idx += stride){
        g_c[idx] = 0.f;
        g_h[idx] = 0.f;
        g_A16[(idx >> 9)*KG_ + 256 + (idx & 511)] = __float2half(0.f);
    }
    if (tid0 < NG_){
        int j = tid0 >> 2, g = tid0 & 3;
        int no = g*512 + j;
        g_bgR[tid0] = bih[no] + bhh[no];
    }
    if (tid0 < 128)
        g_wfdiag[tid0] = __half2float(__float2half(Wf[tid0*F_ + tid0]));
}

// ---------------- delta scan + gamma_x + alpha-input (fused) ----------------
__global__ void k_delta2(const int* __restrict__ mask, const float* __restrict__ Wdx,
                         const float* __restrict__ bdx){
    int idx = blockIdx.x*blockDim.x + threadIdx.x;
    int b = idx >> 7, f = idx & 127;
    const float wdx = Wdx[f*F_ + f];
    const float bx  = bdx[f];
    const int base = b*T_*F_ + f;
    float d = 0.f;
    for (int t = 0; t < T_; t++){
        int o = t*B_ + b;
        g_d16[o*F_ + f] = __float2half(d);
        float gx = expf(-fmaxf(d*wdx + bx, 0.f));
        float mp = (float)mask[base + t*F_];
        g_A216[o*256 + f]       = __float2half(gx);
        g_A216[o*256 + 128 + f] = __float2half(mp);
        d = mp + (1.f - mp)*(d + 1.f);
    }
}

// ---------------- 2-pass fp16 GEMM (precompute) ----------------
#define SSTR 72
#define R2P 320
#define B2P (R2P*SSTR)
#define SM2P (2*B2P*2)

template<int EPI>
__global__ void __launch_bounds__(256, 1)
gemm_2p(const __half* __restrict__ A, const __half* __restrict__ W,
        const __half* __restrict__ Wr, const float* __restrict__ bias,
        float* __restrict__ C, int N, int K)
{
    extern __shared__ __align__(16) __half smh[];
    const int tid = threadIdx.x, lane = tid & 31, wid = tid >> 5;
    const int m0 = blockIdx.y*64, n0 = blockIdx.x*128;
    const int wm = (wid & 1)*32, wn = (wid >> 1)*32;
    const int NC = K >> 6;

    float acc1[2][4][4], acc2[2][4][4];
    #pragma unroll
    for (int i=0;i<2;i++)
        #pragma unroll
        for (int j=0;j<4;j++)
            #pragma unroll
            for (int q=0;q<4;q++){ acc1[i][j][q]=0.f; acc2[i][j][q]=0.f; }

    const int aRow = lane & 15;
    const int aCol = ((lane >> 4) & 1) * 8;
    const int bRow = (lane & 7) + ((lane >> 4) & 1) * 8;
    const int bCol = ((lane >> 3) & 1) * 8;

    const __half* s_src[10]; int s_row[10];
    #pragma unroll
    for (int j = 0; j < 10; j++){
        int u = tid + j*256; int r = u >> 3;
        if (r < 64)      { s_src[j] = A;  s_row[j] = m0 + r; }
        else if (r < 192){ s_src[j] = W;  s_row[j] = n0 + r - 64; }
        else             { s_src[j] = Wr; s_row[j] = n0 + r - 192; }
    }

    {
        #pragma unroll
        for (int j = 0; j < 10; j++){
            int u = tid + j*256; int r = u >> 3, c = (u & 7)*8;
            cpasync16(sptr(&smh[r*SSTR + c]), &s_src[j][(size_t)s_row[j]*K + c]);
        }
        asm volatile("cp.async.commit_group;" ::: "memory");
    }

    for (int ch = 0; ch < NC; ch++){
        if (ch + 1 < NC){
            __half* tb = smh + ((ch+1)&1)*B2P;
            const int k1 = (ch+1)*64;
            #pragma unroll
            for (int j = 0; j < 10; j++){
                int u = tid + j*256; int r = u >> 3, c = (u & 7)*8;
                cpasync16(sptr(&tb[r*SSTR + c]), &s_src[j][(size_t)s_row[j]*K + k1 + c]);
            }
            asm volatile("cp.async.commit_group;" ::: "memory");
            asm volatile("cp.async.wait_group 1;" ::: "memory");
        } else {
            asm volatile("cp.async.wait_group 0;" ::: "memory");
        }
        __syncthreads();

        const __half* bb = smh + (ch&1)*B2P;
        const __half* As = bb;
        const __half* Ws = bb + 64*SSTR;
        const __half* Rs = bb + 192*SSTR;

        #pragma unroll
        for (int kk = 0; kk < 64; kk += 16){
            u32 a[2][4], bw[2][4], br[2][4];
            #pragma unroll
            for (int mt = 0; mt < 2; mt++)
                ldsm4(a[mt], sptr(&As[(wm + mt*16 + aRow)*SSTR + kk + aCol]));
            #pragma unroll
            for (int nt = 0; nt < 2; nt++){
                ldsm4(bw[nt], sptr(&Ws[(wn + nt*16 + bRow)*SSTR + kk + bCol]));
                ldsm4(br[nt], sptr(&Rs[(wn + nt*16 + bRow)*SSTR + kk + bCol]));
            }
            #pragma unroll
            for (int mt = 0; mt < 2; mt++)
                #pragma unroll
                for (int nj = 0; nj < 4; nj++){
                    const u32* pw = &bw[nj >> 1][(nj & 1) * 2];
                    const u32* pr = &br[nj >> 1][(nj & 1) * 2];
                    mma16816h(acc1[mt][nj], a[mt], pw[0], pw[1]);
                    mma16816h(acc2[mt][nj], a[mt], pr[0], pr[1]);
                }
        }
        __syncthreads();
    }

    const float rs = 1.f/1024.f;
    #pragma unroll
    for (int mt = 0; mt < 2; mt++){
        int row = m0 + wm + mt*16 + (lane >> 2);
        #pragma unroll
        for (int nj = 0; nj < 4; nj++){
            int col = n0 + wn + nj*8 + (lane & 3)*2;
            float b0v = bias[col], b1v = bias[col+1];
            float v[4] = { acc1[mt][nj][0] + acc2[mt][nj][0]*rs + b0v,
                           acc1[mt][nj][1] + acc2[mt][nj][1]*rs + b1v,
                           acc1[mt][nj][2] + acc2[mt][nj][2]*rs + b0v,
                           acc1[mt][nj][3] + acc2[mt][nj][3]*rs + b1v };
            #pragma unroll
            for (int q = 0; q < 4; q++){
                if (EPI == 1)      v[q] = expf(-fmaxf(v[q], 0.f));
                else if (EPI == 2) v[q] = 1.f/(1.f+expf(-v[q]));
            }
            C[(size_t)row*N + col]         = v[0];
            C[(size_t)row*N + col + 1]     = v[1];
            C[(size_t)(row+8)*N + col]     = v[2];
            C[(size_t)(row+8)*N + col + 1] = v[3];
        }
    }
}

// ---------------- persistent recurrence kernel, 512 threads ----------------
// Phase B: 16 warps, K-parity split (grp0 even chunks / grp1 odd), partials
// merged in smem. Staging via LDG->reg->STS (next pair prefetched in regs).
// smem: [wh2 131072][wf2 32768][wfd 512][phaseA 12288][staging 55296] = 231936 B
#define WH_OFF  0
#define WF_OFF  131072
#define WFD_OFF 163840
#define SCR_A   164352
#define SCR_G   (SCR_A + 12288)
#define BGH     (192*SSTR)           // halfs per parity buffer (13824)
#define SMR     (SCR_G + 2*BGH*2)    // 231936 bytes

__global__ void __launch_bounds__(512, 1)
k_recur(const float* __restrict__ x, const int* __restrict__ mask,
        const float* __restrict__ bh, const float* __restrict__ bf,
        float* __restrict__ out)
{
    extern __shared__ __align__(16) char sm[];
    const int tid = threadIdx.x, lane = tid & 31, wid = tid >> 5;
    const int bid = blockIdx.x;

    __half2* wh2 = (__half2*)(sm + WH_OFF);
    __half2* wf2 = (__half2*)(sm + WF_OFF);
    float*   wfd = (float*)(sm + WFD_OFF);
    float* hs   = (float*)(sm + SCR_A);      // [4][512]
    float* xh_s = hs + 4*512;                // [4][128]
    float* xc_s = xh_s + 4*128;              // [4][128]
    __half* smG = (__half*)(sm + SCR_G);     // 2 parity buffers + Cs overlay

    for (int idx = tid; idx < 256*128; idx += 512) wh2[idx] = g_Wh2[idx];
    for (int idx = tid; idx < 64*128;  idx += 512) wf2[idx] = g_Wf2[idx];
    if (tid < 128) wfd[tid] = g_wfdiag[tid];
    __syncthreads();

    const int b0 = bid << 2;                 // phase A: 4 batches/CTA
    const int m0 = (bid >> 4)*64;            // GEMM tile
    const int n0 = (bid & 15)*128;
    // phase A mapping: one (batch,feature) per thread
    const int pb = tid >> 7;                 // 0..3
    const int pn = tid & 127;
    // phase B mapping: 2 groups x 8 warps
    const int grp  = wid >> 3;               // 0: even chunks, 1: odd
    const int wid4 = wid & 7;
    const int wm = (wid4 & 1)*32, wn = (wid4 >> 1)*32;
    const int aRow = lane & 15;
    const int aCol = ((lane >> 4) & 1) * 8;
    const int bRow = (lane & 7) + ((lane >> 4) & 1) * 8;
    const int bCol = ((lane >> 3) & 1) * 8;

    // staging map: pair = 2 chunks (128 k), 3072 16B-units over 512 threads
    const __half* rowp[6];
    u32 dstoff[6];
    #pragma unroll
    for (int j = 0; j < 6; j++){
        int u = tid + j*512;                 // 0..3071
        int p = (u >= 1536) ? 1 : 0;
        int w = u - p*1536;                  // 0..1535
        int r = w >> 3;                      // 0..191
        int c = (w & 7) * 8;                 // halfs
        const __half* src = (r < 64) ? g_A16 : g_Wg16;
        int row = (r < 64) ? (m0 + r) : (n0 + r - 64);
        rowp[j]   = src + (size_t)row*KG_ + p*64 + c;
        dstoff[j] = (u32)(p*BGH + r*SSTR + c);
    }

    for (int t = 0; t < T_; t++){
        // ===== phase A: x_h, z_h, outputs, A16[c_c|m] (512 threads) =====
        for (int idx = tid; idx < 2048; idx += 512)
            hs[idx] = g_h[b0*H_ + idx];
        __syncthreads();

        float acc = 0.f;
        {
            const float* hrow = hs + pb*512;
            #pragma unroll 8
            for (int k2 = 0; k2 < 256; k2++){
                float2 w = __half22float2(wh2[k2*128 + pn]);
                float2 hv = *(const float2*)(hrow + 2*k2);
                acc += w.x*hv.x + w.y*hv.y;
            }
        }

        float m_r, x_r;
        {
            int gb = b0 + pb;
            float xh = acc + bh[pn];
            xh_s[pb*128 + pn] = xh;
            int gi = gb*T_*F_ + t*F_ + pn;
            m_r = (float)mask[gi];
            x_r = x[gi];
            xc_s[pb*128 + pn] = m_r*x_r + (1.f - m_r)*xh;
            out[3*BTF_ + gi] = xh;
        }
        __syncthreads();

        float acc2 = 0.f;
        {
            const float* crow = xc_s + pb*128;
            #pragma unroll 8
            for (int k2 = 0; k2 < 64; k2++){
                float2 w = __half22float2(wf2[k2*128 + pn]);
                float2 cv = *(const float2*)(crow + 2*k2);
                acc2 += w.x*cv.x + w.y*cv.y;
            }
        }
        {
            int gb = b0 + pb;
            float xc = xc_s[pb*128 + pn];
            float z  = acc2 + bf[pn] - xc*wfd[pn];
            float al = g_alpha[(size_t)(t*B_ + gb)*F_ + pn];
            float xh = xh_s[pb*128 + pn];
            float ch = al*z + (1.f - al)*xh;
            float cc = m_r*x_r + (1.f - m_r)*ch;
            int gi = gb*T_*F_ + t*F_ + pn;
            out[gi]          = cc;
            out[BTF_  + gi]  = ch;
            out[2*BTF_+ gi]  = z;
            g_A16[gb*KG_ + pn]       = __float2half(cc);
            g_A16[gb*KG_ + 128 + pn] = __float2half(m_r);
        }

        gridsync();
        if (t == T_ - 1) break;

        // ===== phase B: gates GEMM K=768, 16 warps, K-parity split =====
        float acc3[2][4][4];
        #pragma unroll
        for (int i=0;i<2;i++)
            #pragma unroll
            for (int j=0;j<4;j++)
                #pragma unroll
                for (int q=0;q<4;q++) acc3[i][j][q] = 0.f;

        uint4 st[6];
        #pragma unroll
        for (int j = 0; j < 6; j++) st[j] = *(const uint4*)rowp[j];

        const __half* bb = smG + grp*BGH;
        const __half* As = bb;
        const __half* Ws = bb + 64*SSTR;

        for (int pair = 0; pair < 6; pair++){
            __syncthreads();                 // buffers free from previous pair
            #pragma unroll
            for (int j = 0; j < 6; j++)
                *(uint4*)&smG[dstoff[j]] = st[j];
            __syncthreads();
            if (pair < 5){
                #pragma unroll
                for (int j = 0; j < 6; j++)
                    st[j] = *(const uint4*)(rowp[j] + (pair+1)*128);
            }
            #pragma unroll
            for (int kk = 0; kk < 64; kk += 16){
                u32 a[2][4], b[2][4];
                #pragma unroll
                for (int mt = 0; mt < 2; mt++)
                    ldsm4(a[mt], sptr(&As[(wm + mt*16 + aRow)*SSTR + kk + aCol]));
                #pragma unroll
                for (int nt = 0; nt < 2; nt++)
                    ldsm4(b[nt], sptr(&Ws[(wn + nt*16 + bRow)*SSTR + kk + bCol]));
                #pragma unroll
                for (int mt = 0; mt < 2; mt++)
                    #pragma unroll
                    for (int nj = 0; nj < 4; nj++){
                        const u32* pbm = &b[nj >> 1][(nj & 1) * 2];
                        mma16816h(acc3[mt][nj], a[mt], pbm[0], pbm[1]);
                    }
            }
        }
        __syncthreads();

        // ---- merge partials + bias into Cs, then LSTM update ----
        float* Cs = (float*)smG;   // 64x128 fp32 overlay
        if (grp == 0){
            #pragma unroll
            for (int mt = 0; mt < 2; mt++){
                int rl = wm + mt*16 + (lane >> 2);
                #pragma unroll
                for (int nj = 0; nj < 4; nj++){
                    int cl = wn + nj*8 + (lane & 3)*2;
                    float b0v = g_bgR[n0 + cl], b1v = g_bgR[n0 + cl + 1];
                    Cs[rl*128 + cl]         = acc3[mt][nj][0] + b0v;
                    Cs[rl*128 + cl + 1]     = acc3[mt][nj][1] + b1v;
                    Cs[(rl+8)*128 + cl]     = acc3[mt][nj][2] + b0v;
                    Cs[(rl+8)*128 + cl + 1] = acc3[mt][nj][3] + b1v;
                }
            }
        }
        __syncthreads();
        if (grp == 1){
            #pragma unroll
            for (int mt = 0; mt < 2; mt++){
                int rl = wm + mt*16 + (lane >> 2);
                #pragma unroll
                for (int nj = 0; nj < 4; nj++){
                    int cl = wn + nj*8 + (lane & 3)*2;
                    Cs[rl*128 + cl]         += acc3[mt][nj][0];
                    Cs[rl*128 + cl + 1]     += acc3[mt][nj][1];
                    Cs[(rl+8)*128 + cl]     += acc3[mt][nj][2];
                    Cs[(rl+8)*128 + cl + 1] += acc3[mt][nj][3];
                }
            }
        }
        __syncthreads();

        const int u0 = n0 >> 2;
        #pragma unroll
        for (int i = 0; i < 4; i++){
            int cidx = tid + i*512;
            int bl = cidx >> 5, jl = cidx & 31;
            float4 gv = *(const float4*)&Cs[bl*128 + jl*4];   // i, f, g, o
            float ig = sigmoidf_(gv.x);
            float fg = sigmoidf_(gv.y);
            float gg = tanhf(gv.z);
            float og = sigmoidf_(gv.w);
            int gb = m0 + bl;
            int ju = u0 + jl;
            float c = fg * g_c[gb*H_ + ju] + ig*gg;
            g_c[gb*H_ + ju] = c;
            float h = og * tanhf(c);
            g_h[gb*H_ + ju] = h;
            float hd = h * g_gammah[(size_t)((t+1)*B_ + gb)*H_ + ju];
            g_A16[gb*KG_ + 256 + ju] = __float2half(hd);
        }

        gridsync();
    }
}

// ---------------- launch ----------------
extern "C" void kernel_launch(void* const* d_in, const int* in_sizes, int n_in,
                              void* d_out, int out_size)
{
    const float* x    = (const float*)d_in[0];
    const int*   mask = (const int*  )d_in[1];
    const float* Wdh  = (const float*)d_in[2];
    const float* bdh  = (const float*)d_in[3];
    const float* Wdx  = (const float*)d_in[4];
    const float* bdx  = (const float*)d_in[5];
    const float* Wh   = (const float*)d_in[6];
    const float* bh   = (const float*)d_in[7];
    const float* Wf   = (const float*)d_in[8];
    const float* bf   = (const float*)d_in[9];
    const float* Wc   = (const float*)d_in[10];
    const float* bc   = (const float*)d_in[11];
    const float* Wih  = (const float*)d_in[12];
    const float* Whh  = (const float*)d_in[13];
    const float* bih  = (const float*)d_in[14];
    const float* bhh  = (const float*)d_in[15];
    float* out = (float*)d_out;

    void *pD16, *pA216, *pWdh16, *pWdhR, *pWc16, *pWcR, *pGammah, *pAlpha;
    cudaGetSymbolAddress(&pD16,    g_d16);
    cudaGetSymbolAddress(&pA216,   g_A216);
    cudaGetSymbolAddress(&pWdh16,  g_Wdh16);
    cudaGetSymbolAddress(&pWdhR,   g_WdhR);
    cudaGetSymbolAddress(&pWc16,   g_Wc16);
    cudaGetSymbolAddress(&pWcR,    g_WcR);
    cudaGetSymbolAddress(&pGammah, g_gammah);
    cudaGetSymbolAddress(&pAlpha,  g_alpha);

    cudaFuncSetAttribute(gemm_2p<1>, cudaFuncAttributeMaxDynamicSharedMemorySize, SM2P);
    cudaFuncSetAttribute(gemm_2p<2>, cudaFuncAttributeMaxDynamicSharedMemorySize, SM2P);
    cudaFuncSetAttribute(k_recur,    cudaFuncAttributeMaxDynamicSharedMemorySize, SMR);

    // setup + time-parallel precomputes
    k_setup<<<2048, 256>>>(Wih, Whh, bih, bhh, Wdh, Wc, Wh, Wf);
    k_delta2<<<256, 256>>>(mask, Wdx, bdx);
    gemm_2p<1><<<dim3(H_/128, TB_/64), 256, SM2P>>>(
        (const __half*)pD16, (const __half*)pWdh16, (const __half*)pWdhR,
        bdh, (float*)pGammah, H_, F_);
    gemm_2p<2><<<dim3(F_/128, TB_/64), 256, SM2P>>>(
        (const __half*)pA216, (const __half*)pWc16, (const __half*)pWcR,
        bc, (float*)pAlpha, F_, 2*F_);

    // entire 96-step recurrence in ONE persistent kernel
    k_recur<<<NCTA, 512, SMR>>>(x, mask, bh, bf, out);
}

// round 17
// speedup vs baseline: 1.1274x; 1.0141x over previous
#include <cuda_runtime.h>
#include <cuda_fp16.h>
#include <cstdint>
#include <math.h>

#define B_ 512
#define T_ 96
#define F_ 128
#define H_ 512
#define TB_ (T_*B_)        // 49152
#define BTF_ (B_*T_*F_)    // 6291456
#define KG_ 768            // gates GEMM K = 2F + H
#define NG_ 2048           // 4H
#define NCTA 128

typedef unsigned int u32;

// ---------------- scratch (device globals: no allocation allowed) ----------------
__device__ __align__(16) __half g_d16[TB_*F_];
__device__ float g_gammah[TB_*H_];
__device__ __align__(16) __half g_A216[TB_*2*F_];
__device__ float g_alpha[TB_*F_];
__device__ __align__(16) __half g_A16[B_*KG_];     // [c_c | m | h*gamma]
__device__ float g_c[B_*H_];
__device__ float g_h[B_*H_];
__device__ __align__(16) __half g_Wg16[NG_*KG_];   // gate-interleaved
__device__ float g_bgR[NG_];
__device__ __align__(16) __half g_Wdh16[H_*F_];
__device__ __align__(16) __half g_WdhR[H_*F_];
__device__ __align__(16) __half g_Wc16[F_*2*F_];
__device__ __align__(16) __half g_WcR[F_*2*F_];
__device__ __align__(16) __half2 g_Wh2[256*128];   // Wh packed [k2][n]
__device__ __align__(16) __half2 g_Wf2[64*128];    // Wf packed [k2][n]
__device__ float g_wfdiag[128];
__device__ unsigned g_barcnt;
__device__ volatile unsigned g_bargen;

__device__ __forceinline__ float sigmoidf_(float v){ return 1.f/(1.f+expf(-v)); }

__device__ __forceinline__ u32 sptr(const void* p){
    return (u32)__cvta_generic_to_shared(p);
}

__device__ __forceinline__ void ldsm4(u32* r, u32 addr){
    asm volatile("ldmatrix.sync.aligned.m8n8.x4.shared.b16 {%0,%1,%2,%3}, [%4];"
        : "=r"(r[0]),"=r"(r[1]),"=r"(r[2]),"=r"(r[3]) : "r"(addr));
}

__device__ __forceinline__ void mma16816h(float* c, const u32* a, u32 b0, u32 b1){
    asm volatile("mma.sync.aligned.m16n8k16.row.col.f32.f16.f16.f32 "
        "{%0,%1,%2,%3},{%4,%5,%6,%7},{%8,%9},{%0,%1,%2,%3};"
        : "+f"(c[0]),"+f"(c[1]),"+f"(c[2]),"+f"(c[3])
        : "r"(a[0]),"r"(a[1]),"r"(a[2]),"r"(a[3]), "r"(b0),"r"(b1));
}

__device__ __forceinline__ void cpasync16(u32 dst, const void* src){
    asm volatile("cp.async.cg.shared.global [%0], [%1], 16;" :: "r"(dst), "l"(src));
}

__device__ __forceinline__ void gridsync(){
    __syncthreads();
    __threadfence();
    if (threadIdx.x == 0){
        unsigned gen = g_bargen;
        if (atomicAdd(&g_barcnt, 1u) == NCTA-1u){
            g_barcnt = 0;
            __threadfence();
            g_bargen = gen + 1u;
        } else {
            while (g_bargen == gen) { }
        }
    }
    __syncthreads();
    __threadfence();
}

// ---------------- setup ----------------
__global__ void k_setup(const float* __restrict__ Wih, const float* __restrict__ Whh,
                        const float* __restrict__ bih, const float* __restrict__ bhh,
                        const float* __restrict__ Wdh, const float* __restrict__ Wc,
                        const float* __restrict__ Wh, const float* __restrict__ Wf){
    int tid0 = blockIdx.x*blockDim.x + threadIdx.x;
    int stride = gridDim.x*blockDim.x;
    for (int idx = tid0; idx < NG_*KG_; idx += stride){
        int n = idx / KG_;
        int k = idx - n*KG_;
        int j = n >> 2, g = n & 3;
        int no = g*512 + j;
        float v = (k < 256) ? Wih[no*256 + k] : Whh[no*H_ + (k-256)];
        g_Wg16[idx] = __float2half(v);
    }
    for (int idx = tid0; idx < H_*F_; idx += stride){
        float v = Wdh[idx];
        __half h = __float2half(v);
        g_Wdh16[idx] = h;
        g_WdhR[idx]  = __float2half((v - __half2float(h))*1024.f);
    }
    for (int idx = tid0; idx < F_*2*F_; idx += stride){
        float v = Wc[idx];
        __half h = __float2half(v);
        g_Wc16[idx] = h;
        g_WcR[idx]  = __float2half((v - __half2float(h))*1024.f);
    }
    for (int idx = tid0; idx < 256*128; idx += stride){
        int k2 = idx >> 7, n = idx & 127;
        g_Wh2[idx] = __floats2half2_rn(Wh[n*H_ + 2*k2], Wh[n*H_ + 2*k2 + 1]);
    }
    for (int idx = tid0; idx < 64*128; idx += stride){
        int k2 = idx >> 7, n = idx & 127;
        g_Wf2[idx] = __floats2half2_rn(Wf[n*F_ + 2*k2], Wf[n*F_ + 2*k2 + 1]);
    }
    for (int idx = tid0; idx < B_*H_; idx += stride){
        g_c[idx] = 0.f;
        g_h[idx] = 0.f;
        g_A16[(idx >> 9)*KG_ + 256 + (idx & 511)] = __float2half(0.f);
    }
    if (tid0 < NG_){
        int j = tid0 >> 2, g = tid0 & 3;
        int no = g*512 + j;
        g_bgR[tid0] = bih[no] + bhh[no];
    }
    if (tid0 < 128)
        g_wfdiag[tid0] = __half2float(__float2half(Wf[tid0*F_ + tid0]));
}

// ---------------- delta scan + gamma_x + alpha-input (fused) ----------------
__global__ void k_delta2(const int* __restrict__ mask, const float* __restrict__ Wdx,
                         const float* __restrict__ bdx){
    int idx = blockIdx.x*blockDim.x + threadIdx.x;
    int b = idx >> 7, f = idx & 127;
    const float wdx = Wdx[f*F_ + f];
    const float bx  = bdx[f];
    const int base = b*T_*F_ + f;
    float d = 0.f;
    for (int t = 0; t < T_; t++){
        int o = t*B_ + b;
        g_d16[o*F_ + f] = __float2half(d);
        float gx = expf(-fmaxf(d*wdx + bx, 0.f));
        float mp = (float)mask[base + t*F_];
        g_A216[o*256 + f]       = __float2half(gx);
        g_A216[o*256 + 128 + f] = __float2half(mp);
        d = mp + (1.f - mp)*(d + 1.f);
    }
}

// ---------------- 2-pass fp16 GEMM (precompute) ----------------
#define SSTR 72
#define R2P 320
#define B2P (R2P*SSTR)
#define SM2P (2*B2P*2)

template<int EPI>
__global__ void __launch_bounds__(256, 1)
gemm_2p(const __half* __restrict__ A, const __half* __restrict__ W,
        const __half* __restrict__ Wr, const float* __restrict__ bias,
        float* __restrict__ C, int N, int K)
{
    extern __shared__ __align__(16) __half smh[];
    const int tid = threadIdx.x, lane = tid & 31, wid = tid >> 5;
    const int m0 = blockIdx.y*64, n0 = blockIdx.x*128;
    const int wm = (wid & 1)*32, wn = (wid >> 1)*32;
    const int NC = K >> 6;

    float acc1[2][4][4], acc2[2][4][4];
    #pragma unroll
    for (int i=0;i<2;i++)
        #pragma unroll
        for (int j=0;j<4;j++)
            #pragma unroll
            for (int q=0;q<4;q++){ acc1[i][j][q]=0.f; acc2[i][j][q]=0.f; }

    const int aRow = lane & 15;
    const int aCol = ((lane >> 4) & 1) * 8;
    const int bRow = (lane & 7) + ((lane >> 4) & 1) * 8;
    const int bCol = ((lane >> 3) & 1) * 8;

    const __half* s_src[10]; int s_row[10];
    #pragma unroll
    for (int j = 0; j < 10; j++){
        int u = tid + j*256; int r = u >> 3;
        if (r < 64)      { s_src[j] = A;  s_row[j] = m0 + r; }
        else if (r < 192){ s_src[j] = W;  s_row[j] = n0 + r - 64; }
        else             { s_src[j] = Wr; s_row[j] = n0 + r - 192; }
    }

    {
        #pragma unroll
        for (int j = 0; j < 10; j++){
            int u = tid + j*256; int r = u >> 3, c = (u & 7)*8;
            cpasync16(sptr(&smh[r*SSTR + c]), &s_src[j][(size_t)s_row[j]*K + c]);
        }
        asm volatile("cp.async.commit_group;" ::: "memory");
    }

    for (int ch = 0; ch < NC; ch++){
        if (ch + 1 < NC){
            __half* tb = smh + ((ch+1)&1)*B2P;
            const int k1 = (ch+1)*64;
            #pragma unroll
            for (int j = 0; j < 10; j++){
                int u = tid + j*256; int r = u >> 3, c = (u & 7)*8;
                cpasync16(sptr(&tb[r*SSTR + c]), &s_src[j][(size_t)s_row[j]*K + k1 + c]);
            }
            asm volatile("cp.async.commit_group;" ::: "memory");
            asm volatile("cp.async.wait_group 1;" ::: "memory");
        } else {
            asm volatile("cp.async.wait_group 0;" ::: "memory");
        }
        __syncthreads();

        const __half* bb = smh + (ch&1)*B2P;
        const __half* As = bb;
        const __half* Ws = bb + 64*SSTR;
        const __half* Rs = bb + 192*SSTR;

        #pragma unroll
        for (int kk = 0; kk < 64; kk += 16){
            u32 a[2][4], bw[2][4], br[2][4];
            #pragma unroll
            for (int mt = 0; mt < 2; mt++)
                ldsm4(a[mt], sptr(&As[(wm + mt*16 + aRow)*SSTR + kk + aCol]));
            #pragma unroll
            for (int nt = 0; nt < 2; nt++){
                ldsm4(bw[nt], sptr(&Ws[(wn + nt*16 + bRow)*SSTR + kk + bCol]));
                ldsm4(br[nt], sptr(&Rs[(wn + nt*16 + bRow)*SSTR + kk + bCol]));
            }
            #pragma unroll
            for (int mt = 0; mt < 2; mt++)
                #pragma unroll
                for (int nj = 0; nj < 4; nj++){
                    const u32* pw = &bw[nj >> 1][(nj & 1) * 2];
                    const u32* pr = &br[nj >> 1][(nj & 1) * 2];
                    mma16816h(acc1[mt][nj], a[mt], pw[0], pw[1]);
                    mma16816h(acc2[mt][nj], a[mt], pr[0], pr[1]);
                }
        }
        __syncthreads();
    }

    const float rs = 1.f/1024.f;
    #pragma unroll
    for (int mt = 0; mt < 2; mt++){
        int row = m0 + wm + mt*16 + (lane >> 2);
        #pragma unroll
        for (int nj = 0; nj < 4; nj++){
            int col = n0 + wn + nj*8 + (lane & 3)*2;
            float b0v = bias[col], b1v = bias[col+1];
            float v[4] = { acc1[mt][nj][0] + acc2[mt][nj][0]*rs + b0v,
                           acc1[mt][nj][1] + acc2[mt][nj][1]*rs + b1v,
                           acc1[mt][nj][2] + acc2[mt][nj][2]*rs + b0v,
                           acc1[mt][nj][3] + acc2[mt][nj][3]*rs + b1v };
            #pragma unroll
            for (int q = 0; q < 4; q++){
                if (EPI == 1)      v[q] = expf(-fmaxf(v[q], 0.f));
                else if (EPI == 2) v[q] = 1.f/(1.f+expf(-v[q]));
            }
            C[(size_t)row*N + col]         = v[0];
            C[(size_t)row*N + col + 1]     = v[1];
            C[(size_t)(row+8)*N + col]     = v[2];
            C[(size_t)(row+8)*N + col + 1] = v[3];
        }
    }
}

// ---------------- persistent recurrence kernel, 512 threads ----------------
// Per step: [hγ-GEMM (K=256..768, 4 pairs) interleaved with phase-A FFMA]
//           -> gridsync -> [c|m-GEMM (K=0..256, 2 pairs)] -> merge/LSTM -> gridsync
// smem: [wh2 131072][wf2 32768][wfd 512][phaseA 12288][staging 55296] = 231936 B
#define WH_OFF  0
#define WF_OFF  131072
#define WFD_OFF 163840
#define SCR_A   164352
#define SCR_G   (SCR_A + 12288)
#define BGH     (192*SSTR)           // halfs per parity buffer (13824)
#define SMR     (SCR_G + 2*BGH*2)    // 231936 bytes

__global__ void __launch_bounds__(512, 1)
k_recur(const float* __restrict__ x, const int* __restrict__ mask,
        const float* __restrict__ bh, const float* __restrict__ bf,
        float* __restrict__ out)
{
    extern __shared__ __align__(16) char sm[];
    const int tid = threadIdx.x, lane = tid & 31, wid = tid >> 5;
    const int bid = blockIdx.x;

    __half2* wh2 = (__half2*)(sm + WH_OFF);
    __half2* wf2 = (__half2*)(sm + WF_OFF);
    float*   wfd = (float*)(sm + WFD_OFF);
    float* hs   = (float*)(sm + SCR_A);      // [4][512]
    float* xh_s = hs + 4*512;                // [4][128]
    float* xc_s = xh_s + 4*128;              // [4][128]
    __half* smG = (__half*)(sm + SCR_G);     // 2 parity buffers + Cs overlay

    for (int idx = tid; idx < 256*128; idx += 512) wh2[idx] = g_Wh2[idx];
    for (int idx = tid; idx < 64*128;  idx += 512) wf2[idx] = g_Wf2[idx];
    if (tid < 128) wfd[tid] = g_wfdiag[tid];
    __syncthreads();

    const int b0 = bid << 2;                 // phase A: 4 batches/CTA
    const int m0 = (bid >> 4)*64;            // GEMM tile
    const int n0 = (bid & 15)*128;
    const int pb = tid >> 7;                 // phase A batch 0..3
    const int pn = tid & 127;                // phase A feature
    const int grp  = wid >> 3;               // K parity group
    const int wid4 = wid & 7;
    const int wm = (wid4 & 1)*32, wn = (wid4 >> 1)*32;
    const int aRow = lane & 15;
    const int aCol = ((lane >> 4) & 1) * 8;
    const int bRow = (lane & 7) + ((lane >> 4) & 1) * 8;
    const int bCol = ((lane >> 3) & 1) * 8;

    // staging map: pair = 2 chunks (parity split), 3072 16B-units over 512 threads
    const __half* rowp[6];
    u32 dstoff[6];
    #pragma unroll
    for (int j = 0; j < 6; j++){
        int u = tid + j*512;
        int p = (u >= 1536) ? 1 : 0;
        int w = u - p*1536;
        int r = w >> 3;
        int c = (w & 7) * 8;
        const __half* src = (r < 64) ? g_A16 : g_Wg16;
        int row = (r < 64) ? (m0 + r) : (n0 + r - 64);
        rowp[j]   = src + (size_t)row*KG_ + p*64 + c;
        dstoff[j] = (u32)(p*BGH + r*SSTR + c);
    }

    const __half* As = smG + grp*BGH;
    const __half* Ws = As + 64*SSTR;

    for (int t = 0; t < T_; t++){
        // ---- prefetch h, mask, x for phase A ----
        float hv[4];
        #pragma unroll
        for (int i = 0; i < 4; i++) hv[i] = g_h[b0*H_ + tid + i*512];
        const int gb = b0 + pb;
        const int gi = gb*T_*F_ + t*F_ + pn;
        float m_r = (float)mask[gi];
        float x_r = x[gi];

        if (t == T_ - 1){
            // ---- final step: plain phase A (outputs only) ----
            #pragma unroll
            for (int i = 0; i < 4; i++) hs[tid + i*512] = hv[i];
            __syncthreads();
            float accA = 0.f;
            const float* hrow = hs + pb*512;
            #pragma unroll 8
            for (int k2 = 0; k2 < 256; k2++){
                float2 w = __half22float2(wh2[k2*128 + pn]);
                float2 h2 = *(const float2*)(hrow + 2*k2);
                accA += w.x*h2.x + w.y*h2.y;
            }
            float xh = accA + bh[pn];
            xc_s[pb*128 + pn] = m_r*x_r + (1.f - m_r)*xh;
            out[3*BTF_ + gi] = xh;
            __syncthreads();
            float accZ = 0.f;
            const float* crow = xc_s + pb*128;
            #pragma unroll 8
            for (int k2 = 0; k2 < 64; k2++){
                float2 w = __half22float2(wf2[k2*128 + pn]);
                float2 c2 = *(const float2*)(crow + 2*k2);
                accZ += w.x*c2.x + w.y*c2.y;
            }
            float xc = xc_s[pb*128 + pn];
            float z  = accZ + bf[pn] - xc*wfd[pn];
            float al = g_alpha[(size_t)(t*B_ + gb)*F_ + pn];
            float ch = al*z + (1.f - al)*xh;
            float cc = m_r*x_r + (1.f - m_r)*ch;
            out[gi]          = cc;
            out[BTF_  + gi]  = ch;
            out[2*BTF_+ gi]  = z;
            break;
        }

        // ======== hγ GEMM (4 pairs, K=256..768) interleaved with phase A ========
        float acc3[2][4][4];
        #pragma unroll
        for (int i=0;i<2;i++)
            #pragma unroll
            for (int j=0;j<4;j++)
                #pragma unroll
                for (int q=0;q<4;q++) acc3[i][j][q] = 0.f;

        uint4 st[6];
        #pragma unroll
        for (int j = 0; j < 6; j++) st[j] = *(const uint4*)(rowp[j] + 256);

        float accA = 0.f, accZ = 0.f, xh = 0.f;

        #pragma unroll
        for (int pair = 0; pair < 4; pair++){
            __syncthreads();
            #pragma unroll
            for (int j = 0; j < 6; j++)
                *(uint4*)&smG[dstoff[j]] = st[j];
            if (pair == 0){
                #pragma unroll
                for (int i = 0; i < 4; i++) hs[tid + i*512] = hv[i];
            }
            __syncthreads();
            if (pair < 3){
                #pragma unroll
                for (int j = 0; j < 6; j++)
                    st[j] = *(const uint4*)(rowp[j] + 256 + (pair+1)*128);
            }
            // mma block
            #pragma unroll
            for (int kk = 0; kk < 64; kk += 16){
                u32 a[2][4], b[2][4];
                #pragma unroll
                for (int mt = 0; mt < 2; mt++)
                    ldsm4(a[mt], sptr(&As[(wm + mt*16 + aRow)*SSTR + kk + aCol]));
                #pragma unroll
                for (int nt = 0; nt < 2; nt++)
                    ldsm4(b[nt], sptr(&Ws[(wn + nt*16 + bRow)*SSTR + kk + bCol]));
                #pragma unroll
                for (int mt = 0; mt < 2; mt++)
                    #pragma unroll
                    for (int nj = 0; nj < 4; nj++){
                        const u32* pbm = &b[nj >> 1][(nj & 1) * 2];
                        mma16816h(acc3[mt][nj], a[mt], pbm[0], pbm[1]);
                    }
            }
            // phase-A slice (FFMA fills idle issue slots)
            if (pair == 0 || pair == 1){
                const float* hrow = hs + pb*512;
                const int kb = pair*64;
                #pragma unroll 8
                for (int k2 = kb; k2 < kb + 64; k2++){
                    float2 w = __half22float2(wh2[k2*128 + pn]);
                    float2 h2 = *(const float2*)(hrow + 2*k2);
                    accA += w.x*h2.x + w.y*h2.y;
                }
            } else if (pair == 2){
                const float* hrow = hs + pb*512;
                #pragma unroll 8
                for (int k2 = 128; k2 < 256; k2++){
                    float2 w = __half22float2(wh2[k2*128 + pn]);
                    float2 h2 = *(const float2*)(hrow + 2*k2);
                    accA += w.x*h2.x + w.y*h2.y;
                }
                xh = accA + bh[pn];
                xh_s[pb*128 + pn] = xh;
                xc_s[pb*128 + pn] = m_r*x_r + (1.f - m_r)*xh;
                out[3*BTF_ + gi] = xh;
                // pair3's first __syncthreads() orders xc_s before z_h reads
            } else {
                const float* crow = xc_s + pb*128;
                #pragma unroll 8
                for (int k2 = 0; k2 < 64; k2++){
                    float2 w = __half22float2(wf2[k2*128 + pn]);
                    float2 c2 = *(const float2*)(crow + 2*k2);
                    accZ += w.x*c2.x + w.y*c2.y;
                }
                float xc = xc_s[pb*128 + pn];
                float z  = accZ + bf[pn] - xc*wfd[pn];
                float al = g_alpha[(size_t)(t*B_ + gb)*F_ + pn];
                float ch = al*z + (1.f - al)*xh;
                float cc = m_r*x_r + (1.f - m_r)*ch;
                out[gi]          = cc;
                out[BTF_  + gi]  = ch;
                out[2*BTF_+ gi]  = z;
                g_A16[gb*KG_ + pn]       = __float2half(cc);
                g_A16[gb*KG_ + 128 + pn] = __float2half(m_r);
            }
        }

        gridsync();   // A16[c_c|m] now globally visible

        // ======== c|m GEMM (2 pairs, K=0..256) ========
        #pragma unroll
        for (int j = 0; j < 6; j++) st[j] = *(const uint4*)rowp[j];
        #pragma unroll
        for (int pair = 0; pair < 2; pair++){
            __syncthreads();
            #pragma unroll
            for (int j = 0; j < 6; j++)
                *(uint4*)&smG[dstoff[j]] = st[j];
            __syncthreads();
            if (pair == 0){
                #pragma unroll
                for (int j = 0; j < 6; j++)
                    st[j] = *(const uint4*)(rowp[j] + 128);
            }
            #pragma unroll
            for (int kk = 0; kk < 64; kk += 16){
                u32 a[2][4], b[2][4];
                #pragma unroll
                for (int mt = 0; mt < 2; mt++)
                    ldsm4(a[mt], sptr(&As[(wm + mt*16 + aRow)*SSTR + kk + aCol]));
                #pragma unroll
                for (int nt = 0; nt < 2; nt++)
                    ldsm4(b[nt], sptr(&Ws[(wn + nt*16 + bRow)*SSTR + kk + bCol]));
                #pragma unroll
                for (int mt = 0; mt < 2; mt++)
                    #pragma unroll
                    for (int nj = 0; nj < 4; nj++){
                        const u32* pbm = &b[nj >> 1][(nj & 1) * 2];
                        mma16816h(acc3[mt][nj], a[mt], pbm[0], pbm[1]);
                    }
            }
        }
        __syncthreads();

        // ---- merge partials + bias into Cs, then LSTM update ----
        float* Cs = (float*)smG;   // 64x128 fp32 overlay
        if (grp == 0){
            #pragma unroll
            for (int mt = 0; mt < 2; mt++){
                int rl = wm + mt*16 + (lane >> 2);
                #pragma unroll
                for (int nj = 0; nj < 4; nj++){
                    int cl = wn + nj*8 + (lane & 3)*2;
                    float b0v = g_bgR[n0 + cl], b1v = g_bgR[n0 + cl + 1];
                    Cs[rl*128 + cl]         = acc3[mt][nj][0] + b0v;
                    Cs[rl*128 + cl + 1]     = acc3[mt][nj][1] + b1v;
                    Cs[(rl+8)*128 + cl]     = acc3[mt][nj][2] + b0v;
                    Cs[(rl+8)*128 + cl + 1] = acc3[mt][nj][3] + b1v;
                }
            }
        }
        __syncthreads();
        if (grp == 1){
            #pragma unroll
            for (int mt = 0; mt < 2; mt++){
                int rl = wm + mt*16 + (lane >> 2);
                #pragma unroll
                for (int nj = 0; nj < 4; nj++){
                    int cl = wn + nj*8 + (lane & 3)*2;
                    Cs[rl*128 + cl]         += acc3[mt][nj][0];
                    Cs[rl*128 + cl + 1]     += acc3[mt][nj][1];
                    Cs[(rl+8)*128 + cl]     += acc3[mt][nj][2];
                    Cs[(rl+8)*128 + cl + 1] += acc3[mt][nj][3];
                }
            }
        }
        __syncthreads();

        const int u0 = n0 >> 2;
        #pragma unroll
        for (int i = 0; i < 4; i++){
            int cidx = tid + i*512;
            int bl = cidx >> 5, jl = cidx & 31;
            float4 gv = *(const float4*)&Cs[bl*128 + jl*4];   // i, f, g, o
            float ig = sigmoidf_(gv.x);
            float fg = sigmoidf_(gv.y);
            float gg = tanhf(gv.z);
            float og = sigmoidf_(gv.w);
            int gbb = m0 + bl;
            int ju = u0 + jl;
            float c = fg * g_c[gbb*H_ + ju] + ig*gg;
            g_c[gbb*H_ + ju] = c;
            float h = og * tanhf(c);
            g_h[gbb*H_ + ju] = h;
            float hd = h * g_gammah[(size_t)((t+1)*B_ + gbb)*H_ + ju];
            g_A16[gbb*KG_ + 256 + ju] = __float2half(hd);
        }

        gridsync();
    }
}

// ---------------- launch ----------------
extern "C" void kernel_launch(void* const* d_in, const int* in_sizes, int n_in,
                              void* d_out, int out_size)
{
    const float* x    = (const float*)d_in[0];
    const int*   mask = (const int*  )d_in[1];
    const float* Wdh  = (const float*)d_in[2];
    const float* bdh  = (const float*)d_in[3];
    const float* Wdx  = (const float*)d_in[4];
    const float* bdx  = (const float*)d_in[5];
    const float* Wh   = (const float*)d_in[6];
    const float* bh   = (const float*)d_in[7];
    const float* Wf   = (const float*)d_in[8];
    const float* bf   = (const float*)d_in[9];
    const float* Wc   = (const float*)d_in[10];
    const float* bc   = (const float*)d_in[11];
    const float* Wih  = (const float*)d_in[12];
    const float* Whh  = (const float*)d_in[13];
    const float* bih  = (const float*)d_in[14];
    const float* bhh  = (const float*)d_in[15];
    float* out = (float*)d_out;

    void *pD16, *pA216, *pWdh16, *pWdhR, *pWc16, *pWcR, *pGammah, *pAlpha;
    cudaGetSymbolAddress(&pD16,    g_d16);
    cudaGetSymbolAddress(&pA216,   g_A216);
    cudaGetSymbolAddress(&pWdh16,  g_Wdh16);
    cudaGetSymbolAddress(&pWdhR,   g_WdhR);
    cudaGetSymbolAddress(&pWc16,   g_Wc16);
    cudaGetSymbolAddress(&pWcR,    g_WcR);
    cudaGetSymbolAddress(&pGammah, g_gammah);
    cudaGetSymbolAddress(&pAlpha,  g_alpha);

    cudaFuncSetAttribute(gemm_2p<1>, cudaFuncAttributeMaxDynamicSharedMemorySize, SM2P);
    cudaFuncSetAttribute(gemm_2p<2>, cudaFuncAttributeMaxDynamicSharedMemorySize, SM2P);
    cudaFuncSetAttribute(k_recur,    cudaFuncAttributeMaxDynamicSharedMemorySize, SMR);

    // setup + time-parallel precomputes
    k_setup<<<2048, 256>>>(Wih, Whh, bih, bhh, Wdh, Wc, Wh, Wf);
    k_delta2<<<256, 256>>>(mask, Wdx, bdx);
    gemm_2p<1><<<dim3(H_/128, TB_/64), 256, SM2P>>>(
        (const __half*)pD16, (const __half*)pWdh16, (const __half*)pWdhR,
        bdh, (float*)pGammah, H_, F_);
    gemm_2p<2><<<dim3(F_/128, TB_/64), 256, SM2P>>>(
        (const __half*)pA216, (const __half*)pWc16, (const __half*)pWcR,
        bc, (float*)pAlpha, F_, 2*F_);

    // entire 96-step recurrence in ONE persistent kernel
    k_recur<<<NCTA, 512, SMR>>>(x, mask, bh, bf, out);
}